// round 11
// baseline (speedup 1.0000x reference)
#include <cuda_runtime.h>
#include <cuda_fp16.h>

#define F 64
#define MAX_N 50176
#define CAP 128            // max in-degree capacity per node (avg 16, tail ~45)
#define XLD 72             // padded half-stride for W smem tile

// ---- scratch (static device globals; no runtime allocation) ----
__device__ __half2 g_hh[MAX_N * 32];   // h = x @ W, fp16 (32 half2 per row)
__device__ float g_as[MAX_N];          // alpha_src = h @ a_src
__device__ float g_ad[MAX_N];          // alpha_dst = h @ a_dst
__device__ int   g_cursor[MAX_N];      // per-node fill cursor (= final count)
__device__ int2  g_bin[MAX_N * CAP];   // packed (src, __float_as_int(ex)) per edge

// ---------------------------------------------------------------
// h = x @ W via HMMA (m16n8k16). A-fragments loaded DIRECTLY from
// global as float2 (16 independent LDG.64 per thread), converted to
// fp16 in registers. W staged in smem. 64 rows/block, 128 threads.
// Alphas computed from the accumulators in the epilogue.
// ---------------------------------------------------------------
__global__ __launch_bounds__(128) void k_hgemm(
    const float* __restrict__ x, const float* __restrict__ W,
    const float* __restrict__ a_src, const float* __restrict__ a_dst, int N)
{
    __shared__ __half wt[F][XLD];     // W transposed fp16 [n][k]
    int tid  = threadIdx.x;
    int warp = tid >> 5;
    int lane = tid & 31;
    int g = lane >> 2;        // group id (0..7)
    int t = lane & 3;         // thread in group
    int row0 = blockIdx.x * 64 + warp * 16;
    int r1 = row0 + g;
    int r2 = r1 + 8;

    // issue all 16 A-fragment loads up front (independent LDG.64s)
    float2 xa[16];
    #pragma unroll
    for (int ks = 0; ks < 4; ks++) {
        int c0 = ks * 16 + 2 * t;
        xa[ks * 4 + 0] = (r1 < N) ? *(const float2*)&x[r1 * F + c0]     : make_float2(0.f, 0.f);
        xa[ks * 4 + 1] = (r2 < N) ? *(const float2*)&x[r2 * F + c0]     : make_float2(0.f, 0.f);
        xa[ks * 4 + 2] = (r1 < N) ? *(const float2*)&x[r1 * F + c0 + 8] : make_float2(0.f, 0.f);
        xa[ks * 4 + 3] = (r2 < N) ? *(const float2*)&x[r2 * F + c0 + 8] : make_float2(0.f, 0.f);
    }

    // zero fill-cursors (grid*128 >= N; ordered before k_fill by kernel boundary)
    int zi = blockIdx.x * 128 + tid;
    if (zi < N) g_cursor[zi] = 0;

    // W[k][n] -> wt[n][k] fp16 (coalesced read; tiny, L2-hot)
    for (int i = tid; i < F * F; i += 128) {
        int k = i >> 6, n = i & 63;
        wt[n][k] = __float2half_rn(W[i]);
    }
    __syncthreads();

    // convert A fragments to packed half2
    unsigned A[16];
    #pragma unroll
    for (int i = 0; i < 16; i++) {
        __half2 hv = __floats2half2_rn(xa[i].x, xa[i].y);
        A[i] = *(unsigned*)&hv;
    }

    float acc[8][4];
    #pragma unroll
    for (int nf = 0; nf < 8; nf++)
        #pragma unroll
        for (int c = 0; c < 4; c++) acc[nf][c] = 0.f;

    #pragma unroll
    for (int ks = 0; ks < 4; ks++) {
        int ak = ks * 16 + 2 * t;
        #pragma unroll
        for (int nf = 0; nf < 8; nf++) {
            int bn = nf * 8 + g;
            unsigned b0 = *(const unsigned*)&wt[bn][ak];
            unsigned b1 = *(const unsigned*)&wt[bn][ak + 8];
            asm volatile(
                "mma.sync.aligned.m16n8k16.row.col.f32.f16.f16.f32 "
                "{%0,%1,%2,%3}, {%4,%5,%6,%7}, {%8,%9}, {%0,%1,%2,%3};"
                : "+f"(acc[nf][0]), "+f"(acc[nf][1]), "+f"(acc[nf][2]), "+f"(acc[nf][3])
                : "r"(A[ks * 4 + 0]), "r"(A[ks * 4 + 1]),
                  "r"(A[ks * 4 + 2]), "r"(A[ks * 4 + 3]),
                  "r"(b0), "r"(b1));
        }
    }

    // epilogue: thread (g,t) holds rows r1,r2; cols nf*8+2t, nf*8+2t+1.
    float s1 = 0.f, d1 = 0.f, s2 = 0.f, d2 = 0.f;
    #pragma unroll
    for (int nf = 0; nf < 8; nf++) {
        int c = nf * 8 + 2 * t;
        float sa0 = a_src[c], sa1 = a_src[c + 1];
        float da0 = a_dst[c], da1 = a_dst[c + 1];
        s1 += acc[nf][0] * sa0 + acc[nf][1] * sa1;
        d1 += acc[nf][0] * da0 + acc[nf][1] * da1;
        s2 += acc[nf][2] * sa0 + acc[nf][3] * sa1;
        d2 += acc[nf][2] * da0 + acc[nf][3] * da1;
        int cc = nf * 4 + t;     // half2 column index
        if (r1 < N) g_hh[r1 * 32 + cc] = __floats2half2_rn(acc[nf][0], acc[nf][1]);
        if (r2 < N) g_hh[r2 * 32 + cc] = __floats2half2_rn(acc[nf][2], acc[nf][3]);
    }
    #pragma unroll
    for (int off = 2; off; off >>= 1) {
        s1 += __shfl_down_sync(0xffffffffu, s1, off, 4);
        d1 += __shfl_down_sync(0xffffffffu, d1, off, 4);
        s2 += __shfl_down_sync(0xffffffffu, s2, off, 4);
        d2 += __shfl_down_sync(0xffffffffu, d2, off, 4);
    }
    if (t == 0) {
        if (r1 < N) { g_as[r1] = s1; g_ad[r1] = d1; }
        if (r2 < N) { g_as[r2] = s2; g_ad[r2] = d2; }
    }
}

// ---------------------------------------------------------------
// fill bins: 2 edges per thread (coalesced int2 index loads).
// ex = exp(leakyrelu(as[s]+ad[d])); append (s, ex) to dst's slots.
// ---------------------------------------------------------------
__global__ void k_fill(const int* __restrict__ ei, int E) {
    int i0 = (blockIdx.x * blockDim.x + threadIdx.x) * 2;
    if (i0 >= E) return;
    if (i0 + 1 < E) {
        int2 ss = *(const int2*)&ei[i0];
        int2 dd = *(const int2*)&ei[E + i0];
        float v0 = g_as[ss.x] + g_ad[dd.x];
        float v1 = g_as[ss.y] + g_ad[dd.y];
        v0 = (v0 > 0.f) ? v0 : 0.2f * v0;
        v1 = (v1 > 0.f) ? v1 : 0.2f * v1;
        float e0 = __expf(v0), e1 = __expf(v1);
        int p0 = atomicAdd(&g_cursor[dd.x], 1);
        g_bin[dd.x * CAP + p0] = make_int2(ss.x, __float_as_int(e0));
        int p1 = atomicAdd(&g_cursor[dd.y], 1);
        g_bin[dd.y * CAP + p1] = make_int2(ss.y, __float_as_int(e1));
    } else {
        int s = ei[i0], d = ei[E + i0];
        float v = g_as[s] + g_ad[d];
        v = (v > 0.f) ? v : 0.2f * v;
        float ex = __expf(v);
        int p = atomicAdd(&g_cursor[d], 1);
        g_bin[d * CAP + p] = make_int2(s, __float_as_int(ex));
    }
}

// ---------------------------------------------------------------
// gather v3: one warp per node, 4 edges per iteration.
// sub = lane>>3 selects the edge; q = lane&7 owns features 8q..8q+7
// (one uint4 = 8 halves). Tail handled by predication (ej=0).
// Merge via shfl_xor(8|16); lanes 0-7 write the row. No atomics.
// ---------------------------------------------------------------
__global__ __launch_bounds__(256) void k_gather(
    float* __restrict__ out, const float* __restrict__ bias, int N)
{
    int d = (blockIdx.x * 256 + threadIdx.x) >> 5;
    int lane = threadIdx.x & 31;
    if (d >= N) return;
    int sub = lane >> 3;      // edge slot within quad (0..3)
    int q   = lane & 7;       // feature octet

    float4 a0 = make_float4(0.f, 0.f, 0.f, 0.f);
    float4 a1 = make_float4(0.f, 0.f, 0.f, 0.f);
    float den = 0.f;

    if (sub == 0) {           // self loop counted once (sub-group 0)
        float vs = g_as[d] + g_ad[d];
        vs = (vs > 0.f) ? vs : 0.2f * vs;
        float e0 = __expf(vs);
        uint4 hv = *(const uint4*)&g_hh[d * 32 + q * 4];
        float2 u0 = __half22float2(*(__half2*)&hv.x);
        float2 u1 = __half22float2(*(__half2*)&hv.y);
        float2 u2 = __half22float2(*(__half2*)&hv.z);
        float2 u3 = __half22float2(*(__half2*)&hv.w);
        a0 = make_float4(e0 * u0.x, e0 * u0.y, e0 * u1.x, e0 * u1.y);
        a1 = make_float4(e0 * u2.x, e0 * u2.y, e0 * u3.x, e0 * u3.y);
        den = e0;
    }

    const int2* bin = &g_bin[d * CAP];
    int cnt = g_cursor[d];

    #pragma unroll 2
    for (int j = 0; j < cnt; j += 4) {
        int idx = j + sub;
        bool valid = idx < cnt;
        int2 m = valid ? bin[idx] : make_int2(d, 0);
        float ej = valid ? __int_as_float(m.y) : 0.f;
        uint4 hv = *(const uint4*)&g_hh[m.x * 32 + q * 4];
        float2 u0 = __half22float2(*(__half2*)&hv.x);
        float2 u1 = __half22float2(*(__half2*)&hv.y);
        float2 u2 = __half22float2(*(__half2*)&hv.z);
        float2 u3 = __half22float2(*(__half2*)&hv.w);
        a0.x += ej * u0.x; a0.y += ej * u0.y;
        a0.z += ej * u1.x; a0.w += ej * u1.y;
        a1.x += ej * u2.x; a1.y += ej * u2.y;
        a1.z += ej * u3.x; a1.w += ej * u3.y;
        den += ej;
    }

    // merge the 4 sub-groups (reduce over lane bits 3,4)
    #pragma unroll
    for (int off = 8; off <= 16; off <<= 1) {
        den  += __shfl_xor_sync(0xffffffffu, den,  off);
        a0.x += __shfl_xor_sync(0xffffffffu, a0.x, off);
        a0.y += __shfl_xor_sync(0xffffffffu, a0.y, off);
        a0.z += __shfl_xor_sync(0xffffffffu, a0.z, off);
        a0.w += __shfl_xor_sync(0xffffffffu, a0.w, off);
        a1.x += __shfl_xor_sync(0xffffffffu, a1.x, off);
        a1.y += __shfl_xor_sync(0xffffffffu, a1.y, off);
        a1.z += __shfl_xor_sync(0xffffffffu, a1.z, off);
        a1.w += __shfl_xor_sync(0xffffffffu, a1.w, off);
    }

    if (sub == 0) {
        float inv = 1.f / den;
        float4 b0 = *(const float4*)&bias[q * 8];
        float4 b1 = *(const float4*)&bias[q * 8 + 4];
        float4 o0 = make_float4(a0.x * inv + b0.x, a0.y * inv + b0.y,
                                a0.z * inv + b0.z, a0.w * inv + b0.w);
        float4 o1 = make_float4(a1.x * inv + b1.x, a1.y * inv + b1.y,
                                a1.z * inv + b1.z, a1.w * inv + b1.w);
        *(float4*)&out[d * F + q * 8]     = o0;
        *(float4*)&out[d * F + q * 8 + 4] = o1;
    }
}

// ---------------------------------------------------------------
extern "C" void kernel_launch(void* const* d_in, const int* in_sizes, int n_in,
                              void* d_out, int out_size) {
    const float* x     = (const float*)d_in[0];
    const float* W     = (const float*)d_in[1];
    const float* a_src = (const float*)d_in[2];
    const float* a_dst = (const float*)d_in[3];
    const float* bias  = (const float*)d_in[4];
    const int*   ei    = (const int*)d_in[5];
    float* out = (float*)d_out;

    int N = in_sizes[0] / F;
    int E = in_sizes[5] / 2;

    k_hgemm <<<(N + 63) / 64, 128>>>(x, W, a_src, a_dst, N);
    k_fill  <<<((E + 1) / 2 + 255) / 256, 256>>>(ei, E);
    k_gather<<<((long long)N * 32 + 255) / 256, 256>>>(out, bias, N);
}

// round 12
// speedup vs baseline: 1.0038x; 1.0038x over previous
#include <cuda_runtime.h>
#include <cuda_fp16.h>

#define F 64
#define MAX_N 50176
#define CAP 128            // max in-degree capacity per node (avg 16, tail ~45)
#define XLD 72             // padded half-stride for W smem tile

// ---- scratch (static device globals; no runtime allocation) ----
__device__ __half2 g_hh[MAX_N * 32];   // h = x @ W, fp16 (32 half2 per row)
__device__ float g_as[MAX_N];          // alpha_src = h @ a_src
__device__ float g_ad[MAX_N];          // alpha_dst = h @ a_dst
__device__ int   g_cursor[MAX_N];      // per-node fill cursor (= final count)
__device__ int2  g_bin[MAX_N * CAP];   // packed (src, __float_as_int(ex)) per edge

// ---------------------------------------------------------------
// h = x @ W via HMMA (m16n8k16), A loaded directly from global as
// float4 using a k-permutation: thread t owns physical cols
// 4t..4t+3 of each 16-wide k-step, mapped to logical fragment
// positions {2t,2t+1, 8+2t,8+2t+1}. W is staged into smem in the
// SAME logical order, so the product is unchanged (k-order is an
// arbitrary reduction order). 8 LDG.128 per thread (was 16 LDG.64).
// 128 rows x 64 cols per block, 256 threads.
// Alphas computed from the accumulators in the epilogue
// (C-fragment layout is independent of the k-perm).
// ---------------------------------------------------------------
__global__ __launch_bounds__(256) void k_hgemm(
    const float* __restrict__ x, const float* __restrict__ W,
    const float* __restrict__ a_src, const float* __restrict__ a_dst, int N)
{
    __shared__ __half wt[F][XLD];     // W fp16, k logically permuted
    int tid  = threadIdx.x;
    int warp = tid >> 5;
    int lane = tid & 31;
    int g = lane >> 2;        // group id (0..7)
    int t = lane & 3;         // thread in group
    int row0 = blockIdx.x * 128 + warp * 16;
    int r1 = row0 + g;
    int r2 = r1 + 8;

    // issue all 8 A-fragment loads up front (independent LDG.128s)
    float4 xa1[4], xa2[4];
    #pragma unroll
    for (int ks = 0; ks < 4; ks++) {
        int c0 = ks * 16 + 4 * t;
        xa1[ks] = (r1 < N) ? *(const float4*)&x[r1 * F + c0] : make_float4(0.f, 0.f, 0.f, 0.f);
        xa2[ks] = (r2 < N) ? *(const float4*)&x[r2 * F + c0] : make_float4(0.f, 0.f, 0.f, 0.f);
    }

    // zero fill-cursors (grid*256 >= N; ordered before k_fill by kernel boundary)
    int zi = blockIdx.x * 256 + tid;
    if (zi < N) g_cursor[zi] = 0;

    // W[k][n] -> wt[n][logical(k)] fp16.
    // physical k = base16 + 4*tq + e  (tq=0..3, e=0..3)
    // logical  l = base16 + (e<2 ? 2*tq+e : 8+2*tq+(e-2))
    for (int i = tid; i < F * F; i += 256) {
        int k = i >> 6, n = i & 63;
        int base = k & ~15;
        int tq = (k & 15) >> 2;
        int e  = k & 3;
        int l  = base + ((e < 2) ? (2 * tq + e) : (8 + 2 * tq + (e - 2)));
        wt[n][l] = __float2half_rn(W[i]);
    }
    __syncthreads();

    // pack A fragments: (x,y) -> logical {2t,2t+1}; (z,w) -> {8+2t,8+2t+1}
    unsigned A0[4], A1[4], A2[4], A3[4];
    #pragma unroll
    for (int ks = 0; ks < 4; ks++) {
        __half2 h;
        h = __floats2half2_rn(xa1[ks].x, xa1[ks].y); A0[ks] = *(unsigned*)&h;
        h = __floats2half2_rn(xa2[ks].x, xa2[ks].y); A1[ks] = *(unsigned*)&h;
        h = __floats2half2_rn(xa1[ks].z, xa1[ks].w); A2[ks] = *(unsigned*)&h;
        h = __floats2half2_rn(xa2[ks].z, xa2[ks].w); A3[ks] = *(unsigned*)&h;
    }

    float acc[8][4];
    #pragma unroll
    for (int nf = 0; nf < 8; nf++)
        #pragma unroll
        for (int c = 0; c < 4; c++) acc[nf][c] = 0.f;

    #pragma unroll
    for (int ks = 0; ks < 4; ks++) {
        int ak = ks * 16 + 2 * t;     // logical index into wt
        #pragma unroll
        for (int nf = 0; nf < 8; nf++) {
            int bn = nf * 8 + g;
            unsigned b0 = *(const unsigned*)&wt[bn][ak];
            unsigned b1 = *(const unsigned*)&wt[bn][ak + 8];
            asm volatile(
                "mma.sync.aligned.m16n8k16.row.col.f32.f16.f16.f32 "
                "{%0,%1,%2,%3}, {%4,%5,%6,%7}, {%8,%9}, {%0,%1,%2,%3};"
                : "+f"(acc[nf][0]), "+f"(acc[nf][1]), "+f"(acc[nf][2]), "+f"(acc[nf][3])
                : "r"(A0[ks]), "r"(A1[ks]), "r"(A2[ks]), "r"(A3[ks]),
                  "r"(b0), "r"(b1));
        }
    }

    // epilogue: thread (g,t) holds rows r1,r2; cols nf*8+2t, nf*8+2t+1.
    float s1 = 0.f, d1 = 0.f, s2 = 0.f, d2 = 0.f;
    #pragma unroll
    for (int nf = 0; nf < 8; nf++) {
        int c = nf * 8 + 2 * t;
        float sa0 = a_src[c], sa1 = a_src[c + 1];
        float da0 = a_dst[c], da1 = a_dst[c + 1];
        s1 += acc[nf][0] * sa0 + acc[nf][1] * sa1;
        d1 += acc[nf][0] * da0 + acc[nf][1] * da1;
        s2 += acc[nf][2] * sa0 + acc[nf][3] * sa1;
        d2 += acc[nf][2] * da0 + acc[nf][3] * da1;
        int cc = nf * 4 + t;     // half2 column index
        if (r1 < N) g_hh[r1 * 32 + cc] = __floats2half2_rn(acc[nf][0], acc[nf][1]);
        if (r2 < N) g_hh[r2 * 32 + cc] = __floats2half2_rn(acc[nf][2], acc[nf][3]);
    }
    #pragma unroll
    for (int off = 2; off; off >>= 1) {
        s1 += __shfl_down_sync(0xffffffffu, s1, off, 4);
        d1 += __shfl_down_sync(0xffffffffu, d1, off, 4);
        s2 += __shfl_down_sync(0xffffffffu, s2, off, 4);
        d2 += __shfl_down_sync(0xffffffffu, d2, off, 4);
    }
    if (t == 0) {
        if (r1 < N) { g_as[r1] = s1; g_ad[r1] = d1; }
        if (r2 < N) { g_as[r2] = s2; g_ad[r2] = d2; }
    }
}

// ---------------------------------------------------------------
// fill bins: 2 edges per thread (coalesced int2 index loads).
// ex = exp(leakyrelu(as[s]+ad[d])); append (s, ex) to dst's slots.
// ---------------------------------------------------------------
__global__ void k_fill(const int* __restrict__ ei, int E) {
    int i0 = (blockIdx.x * blockDim.x + threadIdx.x) * 2;
    if (i0 >= E) return;
    if (i0 + 1 < E) {
        int2 ss = *(const int2*)&ei[i0];
        int2 dd = *(const int2*)&ei[E + i0];
        float v0 = g_as[ss.x] + g_ad[dd.x];
        float v1 = g_as[ss.y] + g_ad[dd.y];
        v0 = (v0 > 0.f) ? v0 : 0.2f * v0;
        v1 = (v1 > 0.f) ? v1 : 0.2f * v1;
        float e0 = __expf(v0), e1 = __expf(v1);
        int p0 = atomicAdd(&g_cursor[dd.x], 1);
        g_bin[dd.x * CAP + p0] = make_int2(ss.x, __float_as_int(e0));
        int p1 = atomicAdd(&g_cursor[dd.y], 1);
        g_bin[dd.y * CAP + p1] = make_int2(ss.y, __float_as_int(e1));
    } else {
        int s = ei[i0], d = ei[E + i0];
        float v = g_as[s] + g_ad[d];
        v = (v > 0.f) ? v : 0.2f * v;
        float ex = __expf(v);
        int p = atomicAdd(&g_cursor[d], 1);
        g_bin[d * CAP + p] = make_int2(s, __float_as_int(ex));
    }
}

// ---------------------------------------------------------------
// gather (R10 scheme): one warp per node, 2 edges per iteration.
// lanes 0-15 handle even edge, 16-31 odd edge; lane owns 4 features
// (uint2 = 4 halves). Cross-half merge via shfl_xor(16) at the end.
// ---------------------------------------------------------------
__global__ __launch_bounds__(256) void k_gather(
    float* __restrict__ out, const float* __restrict__ bias, int N)
{
    int d = (blockIdx.x * 256 + threadIdx.x) >> 5;
    int lane = threadIdx.x & 31;
    if (d >= N) return;
    int hi = lane >> 4;       // which edge of the pair
    int fl = lane & 15;       // feature quarter: features 4*fl .. 4*fl+3

    float4 acc = make_float4(0.f, 0.f, 0.f, 0.f);
    float den = 0.f;
    if (hi == 0) {            // self loop counted once (half 0 only)
        float vs = g_as[d] + g_ad[d];
        vs = (vs > 0.f) ? vs : 0.2f * vs;
        float e0 = __expf(vs);
        uint2 hv = *(const uint2*)&g_hh[d * 32 + fl * 2];
        float2 u0 = __half22float2(*(__half2*)&hv.x);
        float2 u1 = __half22float2(*(__half2*)&hv.y);
        acc = make_float4(e0 * u0.x, e0 * u0.y, e0 * u1.x, e0 * u1.y);
        den = e0;
    }

    const int2* bin = &g_bin[d * CAP];
    int cnt = g_cursor[d];

    auto proc = [&](int4 q) {
        int   sj = hi ? q.z : q.x;
        float ej = __int_as_float(hi ? q.w : q.y);
        uint2 hv = *(const uint2*)&g_hh[sj * 32 + fl * 2];
        float2 u0 = __half22float2(*(__half2*)&hv.x);
        float2 u1 = __half22float2(*(__half2*)&hv.y);
        acc.x += ej * u0.x; acc.y += ej * u0.y;
        acc.z += ej * u1.x; acc.w += ej * u1.y;
        den += ej;
    };

    int j = 0;
    for (; j + 8 <= cnt; j += 8) {
        int4 q0 = *(const int4*)&bin[j];
        int4 q1 = *(const int4*)&bin[j + 2];
        int4 q2 = *(const int4*)&bin[j + 4];
        int4 q3 = *(const int4*)&bin[j + 6];
        proc(q0); proc(q1); proc(q2); proc(q3);
    }
    for (; j + 2 <= cnt; j += 2) {
        int4 q = *(const int4*)&bin[j];
        proc(q);
    }
    if (j < cnt) {            // odd leftover: half 1 contributes 0
        int2 m = bin[j];
        int4 q = make_int4(m.x, m.y, m.x, 0);
        proc(q);
    }

    // merge the two halves
    den   += __shfl_xor_sync(0xffffffffu, den,   16);
    acc.x += __shfl_xor_sync(0xffffffffu, acc.x, 16);
    acc.y += __shfl_xor_sync(0xffffffffu, acc.y, 16);
    acc.z += __shfl_xor_sync(0xffffffffu, acc.z, 16);
    acc.w += __shfl_xor_sync(0xffffffffu, acc.w, 16);

    if (hi == 0) {
        float inv = 1.f / den;
        float4 bv = *(const float4*)&bias[fl * 4];
        float4 o = make_float4(acc.x * inv + bv.x, acc.y * inv + bv.y,
                               acc.z * inv + bv.z, acc.w * inv + bv.w);
        *(float4*)&out[d * F + fl * 4] = o;
    }
}

// ---------------------------------------------------------------
extern "C" void kernel_launch(void* const* d_in, const int* in_sizes, int n_in,
                              void* d_out, int out_size) {
    const float* x     = (const float*)d_in[0];
    const float* W     = (const float*)d_in[1];
    const float* a_src = (const float*)d_in[2];
    const float* a_dst = (const float*)d_in[3];
    const float* bias  = (const float*)d_in[4];
    const int*   ei    = (const int*)d_in[5];
    float* out = (float*)d_out;

    int N = in_sizes[0] / F;
    int E = in_sizes[5] / 2;

    k_hgemm <<<(N + 127) / 128, 256>>>(x, W, a_src, a_dst, N);
    k_fill  <<<((E + 1) / 2 + 255) / 256, 256>>>(ei, E);
    k_gather<<<((long long)N * 32 + 255) / 256, 256>>>(out, bias, N);
}